// round 16
// baseline (speedup 1.0000x reference)
#include <cuda_runtime.h>
#include <cuda_fp16.h>
#include <cstdint>

#define N_NODES 100000
#define N_PAD   100096          // 782 * 128
#define D_HID   512
#define E_MAX   800000

#define W_OFF_L1 0
#define W_OFF_L2 131072
#define W_OFF_L3 393216
#define W_OFF_FC 655360
#define W_TOTAL  786432

static __device__ __align__(16)  float g_dinv[N_NODES];
static __device__ __align__(256) __half g_bufA[(size_t)N_PAD * D_HID];
static __device__ __align__(256) __half g_bufB[(size_t)N_PAD * D_HID];
static __device__ __align__(256) __half g_w[W_TOTAL];
static __device__ int g_row[E_MAX];
static __device__ int g_col[E_MAX];
static __device__ int g_ideg[N_NODES];
static __device__ int g_rowptr[N_NODES + 1];
static __device__ int g_cursor[N_NODES];
static __device__ int g_csrcol[E_MAX];
static __device__ int g_bsum[128];
static __device__ int g_is32;

// ================================================================ helpers
__device__ __forceinline__ uint32_t smem_u32(const void* p) {
    uint32_t a;
    asm("{ .reg .u64 t; cvta.to.shared.u64 t, %1; cvt.u32.u64 %0, t; }" : "=r"(a) : "l"(p));
    return a;
}
__device__ __forceinline__ void cp16(uint32_t dst, const void* src) {
    asm volatile("cp.async.cg.shared.global [%0], [%1], 16;" :: "r"(dst), "l"(src) : "memory");
}
__device__ __forceinline__ void ldx4(uint32_t r[4], uint32_t addr) {
    asm volatile("ldmatrix.sync.aligned.m8n8.x4.shared.b16 {%0,%1,%2,%3}, [%4];"
                 : "=r"(r[0]), "=r"(r[1]), "=r"(r[2]), "=r"(r[3]) : "r"(addr));
}
__device__ __forceinline__ void mma_f16(float c[4], const uint32_t a[4], uint32_t b0, uint32_t b1) {
    asm volatile("mma.sync.aligned.m16n8k16.row.col.f32.f16.f16.f32 "
                 "{%0,%1,%2,%3}, {%4,%5,%6,%7}, {%8,%9}, {%0,%1,%2,%3};"
                 : "+f"(c[0]), "+f"(c[1]), "+f"(c[2]), "+f"(c[3])
                 : "r"(a[0]), "r"(a[1]), "r"(a[2]), "r"(a[3]), "r"(b0), "r"(b1));
}
__device__ __forceinline__ uint2 pack_h4(float4 v) {
    __half2 p0 = __floats2half2_rn(v.x, v.y);
    __half2 p1 = __floats2half2_rn(v.z, v.w);
    uint2 r;
    r.x = *(uint32_t*)&p0;
    r.y = *(uint32_t*)&p1;
    return r;
}

// ================================================================ fp16 MMA GEMM
// C[nrows,Nout] = A[.,K](fp16) @ W[Nout,K]^T + bias ; out fp16+ReLU (hidden) or fp32 (FC)
// CTA 128x128, 256 thr, 8 warps (4m x 2n), warp tile 32x64, BK=64, 3-stage, 2 CTA/SM.
#define SOFF_A  0
#define SOFF_B  18432           // 128 rows * 144B
#define G_STAGE 36864
#define SMEM_GEMM (3 * G_STAGE) // 110592

__global__ __launch_bounds__(256, 2)
void k_gemm_mma(const __half* __restrict__ A, int K,
                const __half* __restrict__ W,
                void* __restrict__ C, int Nout, const float* __restrict__ bias,
                int nrows, int out_half) {
    extern __shared__ char smem[];
    const uint32_t sb = smem_u32(smem);

    const int tid = threadIdx.x, wid = tid >> 5, lane = tid & 31;
    const int wm = wid & 3, wn = wid >> 2;
    const int bcol = blockIdx.x * 128, brow = blockIdx.y * 128;
    const int nit = K >> 6;

    const int g = lane >> 3, lr = lane & 7;
    const uint32_t a_row = (uint32_t)(wm * 32 + (g & 1) * 8 + lr);
    const uint32_t b_row = (uint32_t)(wn * 64 + (g & 1) * 8 + lr);
    const uint32_t kg = (uint32_t)((g >> 1) * 16);

    float acc[2][8][4];
#pragma unroll
    for (int m = 0; m < 2; m++)
#pragma unroll
        for (int n = 0; n < 8; n++)
#pragma unroll
            for (int v = 0; v < 4; v++) acc[m][n][v] = 0.f;

#define LOAD_STAGE(I) do {                                                              \
    uint32_t _d = sb + ((I) % 3) * G_STAGE; int _k0 = (I) * 64;                         \
    _Pragma("unroll")                                                                   \
    for (int _r = 0; _r < 4; _r++) {                                                    \
        int _c = _r * 256 + tid;                                                        \
        int _row = _c >> 3, _k = _c & 7;                                                \
        cp16(_d + SOFF_A + _row * 144 + _k * 16, A + (size_t)(brow + _row) * K + _k0 + _k * 8); \
        cp16(_d + SOFF_B + _row * 144 + _k * 16, W + (size_t)(bcol + _row) * K + _k0 + _k * 8); \
    }                                                                                   \
    asm volatile("cp.async.commit_group;" ::: "memory");                                \
} while (0)

    LOAD_STAGE(0);
    if (nit > 1) LOAD_STAGE(1);

    for (int i = 0; i < nit; i++) {
        if (i + 2 < nit) {
            LOAD_STAGE(i + 2);
            asm volatile("cp.async.wait_group 2;" ::: "memory");
        } else {
            asm volatile("cp.async.wait_group 0;" ::: "memory");
        }
        __syncthreads();

        const uint32_t base = sb + (i % 3) * G_STAGE;
#pragma unroll
        for (int kst = 0; kst < 4; kst++) {
            const uint32_t acol = kg + kst * 32;
            uint32_t av[2][4];
#pragma unroll
            for (int m = 0; m < 2; m++)
                ldx4(av[m], base + SOFF_A + (a_row + m * 16) * 144 + acol);
#pragma unroll
            for (int p = 0; p < 4; p++) {
                uint32_t bh[4];
                ldx4(bh, base + SOFF_B + (b_row + p * 16) * 144 + acol);
#pragma unroll
                for (int m = 0; m < 2; m++)
#pragma unroll
                    for (int s = 0; s < 2; s++)
                        mma_f16(acc[m][p * 2 + s], av[m], bh[s], bh[s + 2]);
            }
        }
        __syncthreads();
    }
#undef LOAD_STAGE

    const int q = lane >> 2, qt = lane & 3;
    if (out_half) {
        // hidden layer: + bias, ReLU, fp16 out
        __half* Ch = (__half*)C;
#pragma unroll
        for (int m = 0; m < 2; m++) {
            int row = brow + wm * 32 + m * 16 + q;
#pragma unroll
            for (int n = 0; n < 8; n++) {
                int colb = bcol + wn * 64 + n * 8 + qt * 2;
                float* cc = acc[m][n];
                float bx = bias[colb], by = bias[colb + 1];
                float v0 = fmaxf(cc[0] + bx, 0.f), v1 = fmaxf(cc[1] + by, 0.f);
                float v2 = fmaxf(cc[2] + bx, 0.f), v3 = fmaxf(cc[3] + by, 0.f);
                __half2 p0 = __floats2half2_rn(v0, v1);
                __half2 p1 = __floats2half2_rn(v2, v3);
                if (row < nrows)
                    *(uint32_t*)(Ch + (size_t)row * Nout + colb) = *(uint32_t*)&p0;
                if (row + 8 < nrows)
                    *(uint32_t*)(Ch + (size_t)(row + 8) * Nout + colb) = *(uint32_t*)&p1;
            }
        }
    } else {
        // FC: + bias, fp32 out
        float* Cf = (float*)C;
#pragma unroll
        for (int m = 0; m < 2; m++) {
            int row = brow + wm * 32 + m * 16 + q;
#pragma unroll
            for (int n = 0; n < 8; n++) {
                int colb = bcol + wn * 64 + n * 8 + qt * 2;
                float* cc = acc[m][n];
                float bx = bias[colb], by = bias[colb + 1];
                if (row < nrows)
                    *(float2*)(Cf + (size_t)row * Nout + colb) = make_float2(cc[0] + bx, cc[1] + by);
                if (row + 8 < nrows)
                    *(float2*)(Cf + (size_t)(row + 8) * Nout + colb) = make_float2(cc[2] + bx, cc[3] + by);
            }
        }
    }
}

// ================================================================ CSR pull aggregation (pure, pre-GEMM)
// y[n] = dinv[n]*(dinv[n]*x[n] + sum_c dinv[c]*x[c]) over WIDTH cols, fp16 in/out.
template <int NC>  // uint4 chunks per lane: WIDTH = NC*256
__global__ __launch_bounds__(256)
void k_agg_csr(const int* __restrict__ rowptr, const int* __restrict__ csrcol,
               const float* __restrict__ dinv, const __half* __restrict__ x,
               __half* __restrict__ y) {
    const int WIDTH = NC * 256;
    int gw = (int)((blockIdx.x * blockDim.x + threadIdx.x) >> 5);
    int lane = threadIdx.x & 31;
    if (gw >= N_NODES) return;
    int s = __ldg(rowptr + gw), e = __ldg(rowptr + gw + 1);

    float dself = __ldg(dinv + gw);
    float acc[NC * 8];
    const uint4* self = (const uint4*)(x + (size_t)gw * WIDTH);
#pragma unroll
    for (int i = 0; i < NC; i++) {
        uint4 v = __ldg(self + lane + i * 32);
        const __half2* h2 = (const __half2*)&v;
#pragma unroll
        for (int q = 0; q < 4; q++) {
            float2 f = __half22float2(h2[q]);
            acc[i * 8 + q * 2]     = dself * f.x;
            acc[i * 8 + q * 2 + 1] = dself * f.y;
        }
    }

    int j = s;
    for (; j + 1 < e; j += 2) {
        int c0 = __ldg(csrcol + j), c1 = __ldg(csrcol + j + 1);
        float w0 = __ldg(dinv + c0), w1 = __ldg(dinv + c1);
        const uint4* s0 = (const uint4*)(x + (size_t)c0 * WIDTH);
        const uint4* s1 = (const uint4*)(x + (size_t)c1 * WIDTH);
#pragma unroll
        for (int i = 0; i < NC; i++) {
            uint4 v0 = __ldg(s0 + lane + i * 32);
            uint4 v1 = __ldg(s1 + lane + i * 32);
            const __half2* h0 = (const __half2*)&v0;
            const __half2* h1 = (const __half2*)&v1;
#pragma unroll
            for (int q = 0; q < 4; q++) {
                float2 f0 = __half22float2(h0[q]);
                float2 f1 = __half22float2(h1[q]);
                acc[i * 8 + q * 2]     = fmaf(w0, f0.x, fmaf(w1, f1.x, acc[i * 8 + q * 2]));
                acc[i * 8 + q * 2 + 1] = fmaf(w0, f0.y, fmaf(w1, f1.y, acc[i * 8 + q * 2 + 1]));
            }
        }
    }
    if (j < e) {
        int c = __ldg(csrcol + j);
        float w = __ldg(dinv + c);
        const uint4* sv = (const uint4*)(x + (size_t)c * WIDTH);
#pragma unroll
        for (int i = 0; i < NC; i++) {
            uint4 v = __ldg(sv + lane + i * 32);
            const __half2* h2 = (const __half2*)&v;
#pragma unroll
            for (int q = 0; q < 4; q++) {
                float2 f = __half22float2(h2[q]);
                acc[i * 8 + q * 2]     = fmaf(w, f.x, acc[i * 8 + q * 2]);
                acc[i * 8 + q * 2 + 1] = fmaf(w, f.y, acc[i * 8 + q * 2 + 1]);
            }
        }
    }

    size_t obase = (size_t)gw * WIDTH;
#pragma unroll
    for (int i = 0; i < NC; i++) {
        int c = lane + i * 32;
        float4 v0 = make_float4(dself * acc[i * 8 + 0], dself * acc[i * 8 + 1],
                                dself * acc[i * 8 + 2], dself * acc[i * 8 + 3]);
        float4 v1 = make_float4(dself * acc[i * 8 + 4], dself * acc[i * 8 + 5],
                                dself * acc[i * 8 + 6], dself * acc[i * 8 + 7]);
        uint2 lo = pack_h4(v0), hi = pack_h4(v1);
        *(uint4*)(y + obase + (size_t)c * 8) = make_uint4(lo.x, lo.y, hi.x, hi.y);
    }
}

// ================================================================ prep kernels
__global__ void k_prep_all(const float* __restrict__ W1, const float* __restrict__ W2,
                           const float* __restrict__ W3, const float* __restrict__ Wfc,
                           __half* __restrict__ w, int* __restrict__ ideg) {
    int idx = blockIdx.x * blockDim.x + threadIdx.x;
    if (idx == 0) g_is32 = 0;
    if (idx < N_NODES) ideg[idx] = 0;
    if (idx >= W_TOTAL) return;
    const float* W; int K, Nout, base;
    if (idx < W_OFF_L2)      { W = W1;  K = 256; Nout = 512; base = W_OFF_L1; }
    else if (idx < W_OFF_L3) { W = W2;  K = 512; Nout = 512; base = W_OFF_L2; }
    else if (idx < W_OFF_FC) { W = W3;  K = 512; Nout = 512; base = W_OFF_L3; }
    else                     { W = Wfc; K = 512; Nout = 256; base = W_OFF_FC; }
    int local = idx - base;
    int k = local / Nout, n = local - k * Nout;
    w[base + (size_t)n * K + k] = __float2half_rn(W[local]);
}

__global__ void k_detect(const long long* __restrict__ p, int n) {
    int i = blockIdx.x * blockDim.x + threadIdx.x;
    if (i < n) {
        long long v = p[i];
        if (v < 0 || v >= N_NODES) atomicOr(&g_is32, 1);
    }
}
__global__ void k_split(const float4* __restrict__ A, __half* __restrict__ out, int total4) {
    int i = blockIdx.x * blockDim.x + threadIdx.x;
    if (i >= total4) return;
    *(uint2*)(out + (size_t)i * 4) = pack_h4(A[i]);
}
__global__ void k_convert_count(const void* __restrict__ ei, int E,
                                int* __restrict__ row, int* __restrict__ col,
                                int* __restrict__ ideg) {
    int i = blockIdx.x * blockDim.x + threadIdx.x;
    if (i >= E) return;
    int r, c;
    if (g_is32) {
        const int* p = (const int*)ei;
        r = p[i]; c = p[E + i];
    } else {
        const long long* p = (const long long*)ei;
        r = (int)p[i]; c = (int)p[E + i];
    }
    row[i] = r; col[i] = c;
    atomicAdd(&ideg[r], 1);
}

// ---- 3-phase parallel scan
__global__ __launch_bounds__(1024)
void k_scan1(const int* __restrict__ deg, int* __restrict__ rowptr,
             float* __restrict__ dinv, int* __restrict__ bsum, int n) {
    __shared__ int wsum[32];
    int tid = threadIdx.x, w = tid >> 5, lane = tid & 31;
    int idx = blockIdx.x * 1024 + tid;
    int v = (idx < n) ? deg[idx] : 0;
    if (idx < n) dinv[idx] = rsqrtf((float)(v + 1));
    int x = v;
#pragma unroll
    for (int o = 1; o < 32; o <<= 1) {
        int y = __shfl_up_sync(0xFFFFFFFFu, x, o);
        if (lane >= o) x += y;
    }
    if (lane == 31) wsum[w] = x;
    __syncthreads();
    if (w == 0) {
        int orig = wsum[lane];
        int s = orig;
#pragma unroll
        for (int o = 1; o < 32; o <<= 1) {
            int y = __shfl_up_sync(0xFFFFFFFFu, s, o);
            if (lane >= o) s += y;
        }
        wsum[lane] = s - orig;
        if (lane == 31) bsum[blockIdx.x] = s;
    }
    __syncthreads();
    if (idx < n) rowptr[idx] = wsum[w] + x - v;
}
__global__ void k_scan2(int* __restrict__ bsum, int nb) {
    if (threadIdx.x == 0) {
        int run = 0;
        for (int i = 0; i < nb; i++) { int t = bsum[i]; bsum[i] = run; run += t; }
        bsum[nb] = run;
    }
}
__global__ __launch_bounds__(1024)
void k_scan3(int* __restrict__ rowptr, int* __restrict__ cursor,
             const int* __restrict__ bsum, int n) {
    int idx = blockIdx.x * 1024 + threadIdx.x;
    if (idx < n) {
        int r = rowptr[idx] + bsum[blockIdx.x];
        rowptr[idx] = r;
        cursor[idx] = r;
    }
    if (idx == 0) rowptr[n] = bsum[gridDim.x];
}
__global__ void k_csr_scatter(const int* __restrict__ row, const int* __restrict__ col,
                              int* __restrict__ cursor, int* __restrict__ csrcol, int E) {
    int i = blockIdx.x * blockDim.x + threadIdx.x;
    if (i >= E) return;
    int p = atomicAdd(&cursor[row[i]], 1);
    csrcol[p] = col[i];
}

// ================================================================ launch
extern "C" void kernel_launch(void* const* d_in, const int* in_sizes, int n_in,
                              void* d_out, int out_size) {
    const float* x   = (const float*)d_in[0];
    const void*  ei  = d_in[1];
    const float* W1  = (const float*)d_in[2];
    const float* b1  = (const float*)d_in[3];
    const float* W2  = (const float*)d_in[4];
    const float* b2  = (const float*)d_in[5];
    const float* W3  = (const float*)d_in[6];
    const float* b3  = (const float*)d_in[7];
    const float* Wfc = (const float*)d_in[8];
    const float* bfc = (const float*)d_in[9];
    int E = in_sizes[1] / 2;
    if (E > E_MAX) E = E_MAX;

    float* dinv;
    int *row, *col, *ideg, *rowptr, *cursor, *csrcol, *bsum;
    __half *bufA, *bufB, *w;
    cudaGetSymbolAddress((void**)&dinv,   g_dinv);
    cudaGetSymbolAddress((void**)&bufA,   g_bufA);
    cudaGetSymbolAddress((void**)&bufB,   g_bufB);
    cudaGetSymbolAddress((void**)&row,    g_row);
    cudaGetSymbolAddress((void**)&col,    g_col);
    cudaGetSymbolAddress((void**)&ideg,   g_ideg);
    cudaGetSymbolAddress((void**)&rowptr, g_rowptr);
    cudaGetSymbolAddress((void**)&cursor, g_cursor);
    cudaGetSymbolAddress((void**)&csrcol, g_csrcol);
    cudaGetSymbolAddress((void**)&bsum,   g_bsum);
    cudaGetSymbolAddress((void**)&w,      g_w);

    cudaFuncSetAttribute(k_gemm_mma, cudaFuncAttributeMaxDynamicSharedMemorySize, SMEM_GEMM);

    const int T = 256;
    int gE = (E + T - 1) / T;
    int s1 = N_NODES * 256 / 4;
    int nb = (N_NODES + 1023) / 1024;

    dim3 gridH(4, (N_NODES + 127) / 128);   // Nout=512
    dim3 gridO(2, (N_NODES + 127) / 128);   // Nout=256
    int gAgg = (int)(((long long)N_NODES * 32 + T - 1) / T);

    // prep
    k_prep_all<<<(W_TOTAL + T - 1) / T, T>>>(W1, W2, W3, Wfc, w, ideg);
    k_detect<<<gE, T>>>((const long long*)ei, E);
    k_split<<<(s1 + T - 1) / T, T>>>((const float4*)x, bufA, s1);
    k_convert_count<<<gE, T>>>(ei, E, row, col, ideg);
    k_scan1<<<nb, 1024>>>(ideg, rowptr, dinv, bsum, N_NODES);
    k_scan2<<<1, 32>>>(bsum, nb);
    k_scan3<<<nb, 1024>>>(rowptr, cursor, bsum, N_NODES);
    k_csr_scatter<<<gE, T>>>(row, col, cursor, csrcol, E);

    // layer 1: agg(256) -> GEMM(+b1, relu)
    k_agg_csr<1><<<gAgg, T>>>(rowptr, csrcol, dinv, bufA, bufB);
    k_gemm_mma<<<gridH, 256, SMEM_GEMM>>>(bufB, 256, w + W_OFF_L1, bufA, 512, b1, N_NODES, 1);

    // layer 2
    k_agg_csr<2><<<gAgg, T>>>(rowptr, csrcol, dinv, bufA, bufB);
    k_gemm_mma<<<gridH, 256, SMEM_GEMM>>>(bufB, 512, w + W_OFF_L2, bufA, 512, b2, N_NODES, 1);

    // layer 3
    k_agg_csr<2><<<gAgg, T>>>(rowptr, csrcol, dinv, bufA, bufB);
    k_gemm_mma<<<gridH, 256, SMEM_GEMM>>>(bufB, 512, w + W_OFF_L3, bufA, 512, b3, N_NODES, 1);

    // FC (fp32 out + bias, no relu)
    k_gemm_mma<<<gridO, 256, SMEM_GEMM>>>(bufA, 512, w + W_OFF_FC, d_out, 256, bfc, N_NODES, 0);
}

// round 17
// speedup vs baseline: 1.4305x; 1.4305x over previous
#include <cuda_runtime.h>
#include <cuda_fp16.h>
#include <cstdint>

#define N_NODES 100000
#define N_PAD   100096          // 782 * 128
#define D_HID   512
#define E_MAX   800000

#define W_OFF_L1 0
#define W_OFF_L2 131072
#define W_OFF_L3 393216
#define W_OFF_FC 655360
#define W_TOTAL  786432

static __device__ __align__(16)  float g_dinv[N_NODES];
static __device__ __align__(256) __half g_bufA[(size_t)N_PAD * D_HID];
static __device__ __align__(256) __half g_bufB[(size_t)N_PAD * D_HID];
static __device__ __align__(256) __half g_w[W_TOTAL];
static __device__ int g_row[E_MAX];
static __device__ int g_col[E_MAX];
static __device__ int g_ideg[N_NODES];
static __device__ int g_rowptr[N_NODES + 1];
static __device__ int g_cursor[N_NODES];
static __device__ int g_csrcol[E_MAX];
static __device__ int g_bsum[128];
static __device__ int g_is32;

// ================================================================ helpers
__device__ __forceinline__ uint32_t smem_u32(const void* p) {
    uint32_t a;
    asm("{ .reg .u64 t; cvta.to.shared.u64 t, %1; cvt.u32.u64 %0, t; }" : "=r"(a) : "l"(p));
    return a;
}
__device__ __forceinline__ void cp16(uint32_t dst, const void* src) {
    asm volatile("cp.async.cg.shared.global [%0], [%1], 16;" :: "r"(dst), "l"(src) : "memory");
}
__device__ __forceinline__ void ldx4(uint32_t r[4], uint32_t addr) {
    asm volatile("ldmatrix.sync.aligned.m8n8.x4.shared.b16 {%0,%1,%2,%3}, [%4];"
                 : "=r"(r[0]), "=r"(r[1]), "=r"(r[2]), "=r"(r[3]) : "r"(addr));
}
__device__ __forceinline__ void mma_f16(float c[4], const uint32_t a[4], uint32_t b0, uint32_t b1) {
    asm volatile("mma.sync.aligned.m16n8k16.row.col.f32.f16.f16.f32 "
                 "{%0,%1,%2,%3}, {%4,%5,%6,%7}, {%8,%9}, {%0,%1,%2,%3};"
                 : "+f"(c[0]), "+f"(c[1]), "+f"(c[2]), "+f"(c[3])
                 : "r"(a[0]), "r"(a[1]), "r"(a[2]), "r"(a[3]), "r"(b0), "r"(b1));
}
__device__ __forceinline__ uint2 pack_h4(float4 v) {
    __half2 p0 = __floats2half2_rn(v.x, v.y);
    __half2 p1 = __floats2half2_rn(v.z, v.w);
    uint2 r;
    r.x = *(uint32_t*)&p0;
    r.y = *(uint32_t*)&p1;
    return r;
}

// ================================================================ fp16 MMA GEMM
// C[nrows,Nout] = A[.,K](fp16) @ W[Nout,K]^T + bias ; out fp16+ReLU (hidden) or fp32 (FC)
// CTA 128x128, 256 thr, 8 warps (4m x 2n), warp tile 32x64, BK=64, 2-stage, 2 CTA/SM.
#define SOFF_A  0
#define SOFF_B  18432           // 128 rows * 144B
#define G_STAGE 36864
#define SMEM_GEMM (2 * G_STAGE) // 73728

__global__ __launch_bounds__(256, 2)
void k_gemm_mma(const __half* __restrict__ A, int K,
                const __half* __restrict__ W,
                void* __restrict__ C, int Nout, const float* __restrict__ bias,
                int nrows, int out_half) {
    extern __shared__ char smem[];
    const uint32_t sb = smem_u32(smem);

    const int tid = threadIdx.x, wid = tid >> 5, lane = tid & 31;
    const int wm = wid & 3, wn = wid >> 2;
    const int bcol = blockIdx.x * 128, brow = blockIdx.y * 128;
    const int nit = K >> 6;

    const int g = lane >> 3, lr = lane & 7;
    const uint32_t a_row = (uint32_t)(wm * 32 + (g & 1) * 8 + lr);
    const uint32_t b_row = (uint32_t)(wn * 64 + (g & 1) * 8 + lr);
    const uint32_t kg = (uint32_t)((g >> 1) * 16);

    float acc[2][8][4];
#pragma unroll
    for (int m = 0; m < 2; m++)
#pragma unroll
        for (int n = 0; n < 8; n++)
#pragma unroll
            for (int v = 0; v < 4; v++) acc[m][n][v] = 0.f;

#define LOAD_STAGE(I) do {                                                              \
    uint32_t _d = sb + ((I) & 1) * G_STAGE; int _k0 = (I) * 64;                         \
    _Pragma("unroll")                                                                   \
    for (int _r = 0; _r < 4; _r++) {                                                    \
        int _c = _r * 256 + tid;                                                        \
        int _row = _c >> 3, _k = _c & 7;                                                \
        cp16(_d + SOFF_A + _row * 144 + _k * 16, A + (size_t)(brow + _row) * K + _k0 + _k * 8); \
        cp16(_d + SOFF_B + _row * 144 + _k * 16, W + (size_t)(bcol + _row) * K + _k0 + _k * 8); \
    }                                                                                   \
    asm volatile("cp.async.commit_group;" ::: "memory");                                \
} while (0)

    LOAD_STAGE(0);

    for (int i = 0; i < nit; i++) {
        if (i + 1 < nit) {
            LOAD_STAGE(i + 1);
            asm volatile("cp.async.wait_group 1;" ::: "memory");
        } else {
            asm volatile("cp.async.wait_group 0;" ::: "memory");
        }
        __syncthreads();

        const uint32_t base = sb + (i & 1) * G_STAGE;
#pragma unroll
        for (int kst = 0; kst < 4; kst++) {
            const uint32_t acol = kg + kst * 32;
            uint32_t av[2][4];
#pragma unroll
            for (int m = 0; m < 2; m++)
                ldx4(av[m], base + SOFF_A + (a_row + m * 16) * 144 + acol);
#pragma unroll
            for (int p = 0; p < 4; p++) {
                uint32_t bh[4];
                ldx4(bh, base + SOFF_B + (b_row + p * 16) * 144 + acol);
#pragma unroll
                for (int m = 0; m < 2; m++)
#pragma unroll
                    for (int s = 0; s < 2; s++)
                        mma_f16(acc[m][p * 2 + s], av[m], bh[s], bh[s + 2]);
            }
        }
        __syncthreads();
    }
#undef LOAD_STAGE

    const int q = lane >> 2, qt = lane & 3;
    if (out_half) {
        // hidden layer: + bias, ReLU, fp16 out
        __half* Ch = (__half*)C;
#pragma unroll
        for (int m = 0; m < 2; m++) {
            int row = brow + wm * 32 + m * 16 + q;
#pragma unroll
            for (int n = 0; n < 8; n++) {
                int colb = bcol + wn * 64 + n * 8 + qt * 2;
                float* cc = acc[m][n];
                float bx = bias[colb], by = bias[colb + 1];
                float v0 = fmaxf(cc[0] + bx, 0.f), v1 = fmaxf(cc[1] + by, 0.f);
                float v2 = fmaxf(cc[2] + bx, 0.f), v3 = fmaxf(cc[3] + by, 0.f);
                __half2 p0 = __floats2half2_rn(v0, v1);
                __half2 p1 = __floats2half2_rn(v2, v3);
                if (row < nrows)
                    *(uint32_t*)(Ch + (size_t)row * Nout + colb) = *(uint32_t*)&p0;
                if (row + 8 < nrows)
                    *(uint32_t*)(Ch + (size_t)(row + 8) * Nout + colb) = *(uint32_t*)&p1;
            }
        }
    } else {
        // FC: + bias, fp32 out
        float* Cf = (float*)C;
#pragma unroll
        for (int m = 0; m < 2; m++) {
            int row = brow + wm * 32 + m * 16 + q;
#pragma unroll
            for (int n = 0; n < 8; n++) {
                int colb = bcol + wn * 64 + n * 8 + qt * 2;
                float* cc = acc[m][n];
                float bx = bias[colb], by = bias[colb + 1];
                if (row < nrows)
                    *(float2*)(Cf + (size_t)row * Nout + colb) = make_float2(cc[0] + bx, cc[1] + by);
                if (row + 8 < nrows)
                    *(float2*)(Cf + (size_t)(row + 8) * Nout + colb) = make_float2(cc[2] + bx, cc[3] + by);
            }
        }
    }
}

// ================================================================ CSR pull aggregation (pure, pre-GEMM)
// y[n] = dinv[n]*(dinv[n]*x[n] + sum_c dinv[c]*x[c]) over WIDTH cols, fp16 in/out.
template <int NC>  // uint4 chunks per lane: WIDTH = NC*256
__global__ __launch_bounds__(256)
void k_agg_csr(const int* __restrict__ rowptr, const int* __restrict__ csrcol,
               const float* __restrict__ dinv, const __half* __restrict__ x,
               __half* __restrict__ y) {
    const int WIDTH = NC * 256;
    int gw = (int)((blockIdx.x * blockDim.x + threadIdx.x) >> 5);
    int lane = threadIdx.x & 31;
    if (gw >= N_NODES) return;
    int s = __ldg(rowptr + gw), e = __ldg(rowptr + gw + 1);

    float dself = __ldg(dinv + gw);
    float acc[NC * 8];
    const uint4* self = (const uint4*)(x + (size_t)gw * WIDTH);
#pragma unroll
    for (int i = 0; i < NC; i++) {
        uint4 v = __ldg(self + lane + i * 32);
        const __half2* h2 = (const __half2*)&v;
#pragma unroll
        for (int q = 0; q < 4; q++) {
            float2 f = __half22float2(h2[q]);
            acc[i * 8 + q * 2]     = dself * f.x;
            acc[i * 8 + q * 2 + 1] = dself * f.y;
        }
    }

    int j = s;
    for (; j + 1 < e; j += 2) {
        int c0 = __ldg(csrcol + j), c1 = __ldg(csrcol + j + 1);
        float w0 = __ldg(dinv + c0), w1 = __ldg(dinv + c1);
        const uint4* s0 = (const uint4*)(x + (size_t)c0 * WIDTH);
        const uint4* s1 = (const uint4*)(x + (size_t)c1 * WIDTH);
#pragma unroll
        for (int i = 0; i < NC; i++) {
            uint4 v0 = __ldg(s0 + lane + i * 32);
            uint4 v1 = __ldg(s1 + lane + i * 32);
            const __half2* h0 = (const __half2*)&v0;
            const __half2* h1 = (const __half2*)&v1;
#pragma unroll
            for (int q = 0; q < 4; q++) {
                float2 f0 = __half22float2(h0[q]);
                float2 f1 = __half22float2(h1[q]);
                acc[i * 8 + q * 2]     = fmaf(w0, f0.x, fmaf(w1, f1.x, acc[i * 8 + q * 2]));
                acc[i * 8 + q * 2 + 1] = fmaf(w0, f0.y, fmaf(w1, f1.y, acc[i * 8 + q * 2 + 1]));
            }
        }
    }
    if (j < e) {
        int c = __ldg(csrcol + j);
        float w = __ldg(dinv + c);
        const uint4* sv = (const uint4*)(x + (size_t)c * WIDTH);
#pragma unroll
        for (int i = 0; i < NC; i++) {
            uint4 v = __ldg(sv + lane + i * 32);
            const __half2* h2 = (const __half2*)&v;
#pragma unroll
            for (int q = 0; q < 4; q++) {
                float2 f = __half22float2(h2[q]);
                acc[i * 8 + q * 2]     = fmaf(w, f.x, acc[i * 8 + q * 2]);
                acc[i * 8 + q * 2 + 1] = fmaf(w, f.y, acc[i * 8 + q * 2 + 1]);
            }
        }
    }

    size_t obase = (size_t)gw * WIDTH;
#pragma unroll
    for (int i = 0; i < NC; i++) {
        int c = lane + i * 32;
        float4 v0 = make_float4(dself * acc[i * 8 + 0], dself * acc[i * 8 + 1],
                                dself * acc[i * 8 + 2], dself * acc[i * 8 + 3]);
        float4 v1 = make_float4(dself * acc[i * 8 + 4], dself * acc[i * 8 + 5],
                                dself * acc[i * 8 + 6], dself * acc[i * 8 + 7]);
        uint2 lo = pack_h4(v0), hi = pack_h4(v1);
        *(uint4*)(y + obase + (size_t)c * 8) = make_uint4(lo.x, lo.y, hi.x, hi.y);
    }
}

// ================================================================ prep kernels
__global__ void k_prep_all(const float* __restrict__ W1, const float* __restrict__ W2,
                           const float* __restrict__ W3, const float* __restrict__ Wfc,
                           __half* __restrict__ w, int* __restrict__ ideg) {
    int idx = blockIdx.x * blockDim.x + threadIdx.x;
    if (idx == 0) g_is32 = 0;
    if (idx < N_NODES) ideg[idx] = 0;
    if (idx >= W_TOTAL) return;
    const float* W; int K, Nout, base;
    if (idx < W_OFF_L2)      { W = W1;  K = 256; Nout = 512; base = W_OFF_L1; }
    else if (idx < W_OFF_L3) { W = W2;  K = 512; Nout = 512; base = W_OFF_L2; }
    else if (idx < W_OFF_FC) { W = W3;  K = 512; Nout = 512; base = W_OFF_L3; }
    else                     { W = Wfc; K = 512; Nout = 256; base = W_OFF_FC; }
    int local = idx - base;
    int k = local / Nout, n = local - k * Nout;
    w[base + (size_t)n * K + k] = __float2half_rn(W[local]);
}

__global__ void k_detect(const long long* __restrict__ p, int n) {
    int i = blockIdx.x * blockDim.x + threadIdx.x;
    if (i < n) {
        long long v = p[i];
        if (v < 0 || v >= N_NODES) atomicOr(&g_is32, 1);
    }
}
__global__ void k_split(const float4* __restrict__ A, __half* __restrict__ out, int total4) {
    int i = blockIdx.x * blockDim.x + threadIdx.x;
    if (i >= total4) return;
    *(uint2*)(out + (size_t)i * 4) = pack_h4(A[i]);
}
__global__ void k_convert_count(const void* __restrict__ ei, int E,
                                int* __restrict__ row, int* __restrict__ col,
                                int* __restrict__ ideg) {
    int i = blockIdx.x * blockDim.x + threadIdx.x;
    if (i >= E) return;
    int r, c;
    if (g_is32) {
        const int* p = (const int*)ei;
        r = p[i]; c = p[E + i];
    } else {
        const long long* p = (const long long*)ei;
        r = (int)p[i]; c = (int)p[E + i];
    }
    row[i] = r; col[i] = c;
    atomicAdd(&ideg[r], 1);
}

// ---- 3-phase parallel scan
__global__ __launch_bounds__(1024)
void k_scan1(const int* __restrict__ deg, int* __restrict__ rowptr,
             float* __restrict__ dinv, int* __restrict__ bsum, int n) {
    __shared__ int wsum[32];
    int tid = threadIdx.x, w = tid >> 5, lane = tid & 31;
    int idx = blockIdx.x * 1024 + tid;
    int v = (idx < n) ? deg[idx] : 0;
    if (idx < n) dinv[idx] = rsqrtf((float)(v + 1));
    int x = v;
#pragma unroll
    for (int o = 1; o < 32; o <<= 1) {
        int y = __shfl_up_sync(0xFFFFFFFFu, x, o);
        if (lane >= o) x += y;
    }
    if (lane == 31) wsum[w] = x;
    __syncthreads();
    if (w == 0) {
        int orig = wsum[lane];
        int s = orig;
#pragma unroll
        for (int o = 1; o < 32; o <<= 1) {
            int y = __shfl_up_sync(0xFFFFFFFFu, s, o);
            if (lane >= o) s += y;
        }
        wsum[lane] = s - orig;
        if (lane == 31) bsum[blockIdx.x] = s;
    }
    __syncthreads();
    if (idx < n) rowptr[idx] = wsum[w] + x - v;
}
__global__ void k_scan2(int* __restrict__ bsum, int nb) {
    if (threadIdx.x == 0) {
        int run = 0;
        for (int i = 0; i < nb; i++) { int t = bsum[i]; bsum[i] = run; run += t; }
        bsum[nb] = run;
    }
}
__global__ __launch_bounds__(1024)
void k_scan3(int* __restrict__ rowptr, int* __restrict__ cursor,
             const int* __restrict__ bsum, int n) {
    int idx = blockIdx.x * 1024 + threadIdx.x;
    if (idx < n) {
        int r = rowptr[idx] + bsum[blockIdx.x];
        rowptr[idx] = r;
        cursor[idx] = r;
    }
    if (idx == 0) rowptr[n] = bsum[gridDim.x];
}
__global__ void k_csr_scatter(const int* __restrict__ row, const int* __restrict__ col,
                              int* __restrict__ cursor, int* __restrict__ csrcol, int E) {
    int i = blockIdx.x * blockDim.x + threadIdx.x;
    if (i >= E) return;
    int p = atomicAdd(&cursor[row[i]], 1);
    csrcol[p] = col[i];
}

// ================================================================ launch
extern "C" void kernel_launch(void* const* d_in, const int* in_sizes, int n_in,
                              void* d_out, int out_size) {
    const float* x   = (const float*)d_in[0];
    const void*  ei  = d_in[1];
    const float* W1  = (const float*)d_in[2];
    const float* b1  = (const float*)d_in[3];
    const float* W2  = (const float*)d_in[4];
    const float* b2  = (const float*)d_in[5];
    const float* W3  = (const float*)d_in[6];
    const float* b3  = (const float*)d_in[7];
    const float* Wfc = (const float*)d_in[8];
    const float* bfc = (const float*)d_in[9];
    int E = in_sizes[1] / 2;
    if (E > E_MAX) E = E_MAX;

    float* dinv;
    int *row, *col, *ideg, *rowptr, *cursor, *csrcol, *bsum;
    __half *bufA, *bufB, *w;
    cudaGetSymbolAddress((void**)&dinv,   g_dinv);
    cudaGetSymbolAddress((void**)&bufA,   g_bufA);
    cudaGetSymbolAddress((void**)&bufB,   g_bufB);
    cudaGetSymbolAddress((void**)&row,    g_row);
    cudaGetSymbolAddress((void**)&col,    g_col);
    cudaGetSymbolAddress((void**)&ideg,   g_ideg);
    cudaGetSymbolAddress((void**)&rowptr, g_rowptr);
    cudaGetSymbolAddress((void**)&cursor, g_cursor);
    cudaGetSymbolAddress((void**)&csrcol, g_csrcol);
    cudaGetSymbolAddress((void**)&bsum,   g_bsum);
    cudaGetSymbolAddress((void**)&w,      g_w);

    cudaFuncSetAttribute(k_gemm_mma, cudaFuncAttributeMaxDynamicSharedMemorySize, SMEM_GEMM);

    const int T = 256;
    int gE = (E + T - 1) / T;
    int s1 = N_NODES * 256 / 4;
    int nb = (N_NODES + 1023) / 1024;

    dim3 gridH(4, (N_NODES + 127) / 128);   // Nout=512
    dim3 gridO(2, (N_NODES + 127) / 128);   // Nout=256
    int gAgg = (int)(((long long)N_NODES * 32 + T - 1) / T);

    // prep
    k_prep_all<<<(W_TOTAL + T - 1) / T, T>>>(W1, W2, W3, Wfc, w, ideg);
    k_detect<<<gE, T>>>((const long long*)ei, E);
    k_split<<<(s1 + T - 1) / T, T>>>((const float4*)x, bufA, s1);
    k_convert_count<<<gE, T>>>(ei, E, row, col, ideg);
    k_scan1<<<nb, 1024>>>(ideg, rowptr, dinv, bsum, N_NODES);
    k_scan2<<<1, 32>>>(bsum, nb);
    k_scan3<<<nb, 1024>>>(rowptr, cursor, bsum, N_NODES);
    k_csr_scatter<<<gE, T>>>(row, col, cursor, csrcol, E);

    // layer 1: agg(256) -> GEMM(+b1, relu)
    k_agg_csr<1><<<gAgg, T>>>(rowptr, csrcol, dinv, bufA, bufB);
    k_gemm_mma<<<gridH, 256, SMEM_GEMM>>>(bufB, 256, w + W_OFF_L1, bufA, 512, b1, N_NODES, 1);

    // layer 2
    k_agg_csr<2><<<gAgg, T>>>(rowptr, csrcol, dinv, bufA, bufB);
    k_gemm_mma<<<gridH, 256, SMEM_GEMM>>>(bufB, 512, w + W_OFF_L2, bufA, 512, b2, N_NODES, 1);

    // layer 3
    k_agg_csr<2><<<gAgg, T>>>(rowptr, csrcol, dinv, bufA, bufB);
    k_gemm_mma<<<gridH, 256, SMEM_GEMM>>>(bufB, 512, w + W_OFF_L3, bufA, 512, b3, N_NODES, 1);

    // FC (fp32 out + bias, no relu)
    k_gemm_mma<<<gridO, 256, SMEM_GEMM>>>(bufA, 512, w + W_OFF_FC, d_out, 256, bfc, N_NODES, 0);
}